// round 2
// baseline (speedup 1.0000x reference)
#include <cuda_runtime.h>
#include <cuda_fp16.h>
#include <cstdint>
#include <cstddef>

// ---------------- problem constants ----------------
#define BB 32
#define TT 512
#define DD 1024
#define VV 50257
#define SS 16
#define BT (BB*TT)          // 16384
#define D2 (2*DD)           // 2048
#define LN_EPS 1e-5f
#define CONF_TH 0.8f

// ---------------- scratch (device globals; no allocations allowed) ----------------
__device__ float  g_hf32 [ (size_t)BT * DD ];      // residual h (fp32)
__device__ __half g_hh   [ (size_t)BT * DD ];      // h as fp16 (GEMM A)
__device__ __half g_w1h  [ (size_t)DD * D2 ];
__device__ __half g_w2h  [ (size_t)D2 * DD ];
__device__ __half g_act  [ (size_t)BT * D2 ];      // relu(h@W1+b1) fp16
__device__ float  g_x    [ (size_t)BT * DD ];      // h + ff  (pre-LN)
__device__ float  g_stats[ (size_t)BT * 3 ];       // s1, s2, s3 per token
__device__ float  g_gl   [ DD ];                   // ln_g * mean_s(wg_w)
__device__ float  g_scal [ 2 ];                    // {sum_gl, add_const}
__device__ float  g_mem  [ BB * SS * DD ];
__device__ float  g_query[ BB * DD ];
__device__ float  g_q    [ BB * DD ];
__device__ __half g_za   [ 64 * DD ];              // rows 0..31 query, 32..63 ctx (fp16)
__device__ float  g_ld   [ (size_t)BB * VV ];      // direct logits (no bias)
__device__ float  g_lc   [ (size_t)BB * VV ];      // ctx logits (no bias)
__device__ unsigned g_bmax[ BB ];
__device__ float  g_bsum [ BB ];

// ---------------- helpers ----------------
__device__ __forceinline__ void mma16816(float* c, const uint32_t* a, const uint32_t* b) {
    asm volatile(
        "mma.sync.aligned.m16n8k16.row.col.f32.f16.f16.f32 "
        "{%0,%1,%2,%3},{%4,%5,%6,%7},{%8,%9},{%0,%1,%2,%3};\n"
        : "+f"(c[0]), "+f"(c[1]), "+f"(c[2]), "+f"(c[3])
        : "r"(a[0]), "r"(a[1]), "r"(a[2]), "r"(a[3]), "r"(b[0]), "r"(b[1]));
}

__device__ __forceinline__ void atomicMaxFloatEnc(unsigned* addr, float val) {
    unsigned u = __float_as_uint(val);
    unsigned enc = (u & 0x80000000u) ? ~u : (u | 0x80000000u);
    atomicMax(addr, enc);
}
__device__ __forceinline__ float decMax(unsigned enc) {
    unsigned u = (enc & 0x80000000u) ? (enc & 0x7FFFFFFFu) : ~enc;
    return __uint_as_float(u);
}
__device__ __forceinline__ float neg_inf() { return __int_as_float(0xff800000); }

// ---------------- kernels ----------------
__global__ void k_init() {
    int t = threadIdx.x;
    if (t < BB) { g_bmax[t] = 0u; g_bsum[t] = 0.f; }
}

// gl[d] = ln_g[d] * mean_s wg_w[d,s];  scal = {sum_d gl, sum_d ln_b*wgm + mean_s wg_b}
__global__ void k_prep(const float* __restrict__ wg_w, const float* __restrict__ wg_b,
                       const float* __restrict__ ln_g, const float* __restrict__ ln_b) {
    int d = threadIdx.x; // 1024
    float wgm = 0.f;
    #pragma unroll
    for (int s = 0; s < SS; s++) wgm += wg_w[d * SS + s];
    wgm *= (1.f / SS);
    float gl = ln_g[d] * wgm;
    g_gl[d] = gl;
    __shared__ float r1[1024], r2[1024];
    r1[d] = gl; r2[d] = ln_b[d] * wgm;
    __syncthreads();
    for (int s = 512; s > 0; s >>= 1) {
        if (d < s) { r1[d] += r1[d + s]; r2[d] += r2[d + s]; }
        __syncthreads();
    }
    if (d == 0) {
        float wb = 0.f;
        for (int s = 0; s < SS; s++) wb += wg_b[s];
        g_scal[0] = r1[0];
        g_scal[1] = r2[0] + wb * (1.f / SS);
    }
}

__global__ void k_convw(const float* __restrict__ w1, const float* __restrict__ w2) {
    size_t i = (size_t)blockIdx.x * blockDim.x + threadIdx.x;  // 4M threads exact
    const size_t NW = (size_t)DD * D2;
    if (i < NW) g_w1h[i] = __float2half(w1[i]);
    else        g_w2h[i - NW] = __float2half(w2[i - NW]);
}

__global__ void k_gather(const int* __restrict__ seq, const float* __restrict__ embed) {
    int i = blockIdx.x;          // token
    int tid = threadIdx.x;       // 256
    int row = seq[i];
    float4 v = ((const float4*)(embed + (size_t)row * DD))[tid];
    ((float4*)(g_hf32 + (size_t)i * DD))[tid] = v;
    __half2* hp = (__half2*)(g_hh + (size_t)i * DD);
    hp[tid * 2]     = __floats2half2_rn(v.x, v.y);
    hp[tid * 2 + 1] = __floats2half2_rn(v.z, v.w);
}

// MODE 0: act = relu(h@W1+b1)  (fp16 out)     N=2048, K=1024
// MODE 1: x = act@W2 + b2 + h  (fp32 out)     N=1024, K=2048
template<int MODE>
__global__ void __launch_bounds__(256) k_gemm(const float* __restrict__ bias) {
    constexpr int N = (MODE == 0) ? D2 : DD;
    constexpr int K = (MODE == 0) ? DD : D2;
    const __half* __restrict__ A  = (MODE == 0) ? g_hh  : g_act;
    const __half* __restrict__ Bm = (MODE == 0) ? g_w1h : g_w2h;

    constexpr int BM = 128, BN = 128, BK = 32;
    __shared__ __align__(16) __half As[BM * 40];
    __shared__ __align__(16) __half Bs[BN * 34];

    int tid = threadIdx.x;
    int m0 = blockIdx.x * BM, n0 = blockIdx.y * BN;
    int warp = tid >> 5, lane = tid & 31;
    int wm = (warp >> 2) * 64, wn = (warp & 3) * 32;
    int g = lane >> 2, tg = lane & 3;

    float acc[4][4][4];
    #pragma unroll
    for (int a = 0; a < 4; a++)
        #pragma unroll
        for (int b = 0; b < 4; b++)
            #pragma unroll
            for (int c = 0; c < 4; c++) acc[a][b][c] = 0.f;

    for (int k0 = 0; k0 < K; k0 += BK) {
        #pragma unroll
        for (int r = 0; r < 2; r++) {
            int lin = r * 256 + tid;
            int row = lin >> 2, c4 = lin & 3;
            uint4 v = *(const uint4*)(A + (size_t)(m0 + row) * K + k0 + c4 * 8);
            *(uint4*)(As + row * 40 + c4 * 8) = v;
        }
        #pragma unroll
        for (int r = 0; r < 16; r++) {
            int lin = r * 256 + tid;
            int k = lin >> 7, n = lin & 127;
            Bs[n * 34 + k] = Bm[(size_t)(k0 + k) * N + n0 + n];
        }
        __syncthreads();
        #pragma unroll
        for (int kk = 0; kk < BK; kk += 16) {
            uint32_t af[4][4], bf[4][2];
            #pragma unroll
            for (int fm = 0; fm < 4; fm++) {
                const __half* ap = As + (wm + fm * 16) * 40 + kk;
                af[fm][0] = *(const uint32_t*)(ap + g * 40 + tg * 2);
                af[fm][1] = *(const uint32_t*)(ap + (g + 8) * 40 + tg * 2);
                af[fm][2] = *(const uint32_t*)(ap + g * 40 + tg * 2 + 8);
                af[fm][3] = *(const uint32_t*)(ap + (g + 8) * 40 + tg * 2 + 8);
            }
            #pragma unroll
            for (int fn = 0; fn < 4; fn++) {
                const __half* bp = Bs + (wn + fn * 8 + g) * 34 + kk;
                bf[fn][0] = *(const uint32_t*)(bp + tg * 2);
                bf[fn][1] = *(const uint32_t*)(bp + tg * 2 + 8);
            }
            #pragma unroll
            for (int fm = 0; fm < 4; fm++)
                #pragma unroll
                for (int fn = 0; fn < 4; fn++)
                    mma16816(acc[fm][fn], af[fm], bf[fn]);
        }
        __syncthreads();
    }

    #pragma unroll
    for (int fm = 0; fm < 4; fm++) {
        #pragma unroll
        for (int fn = 0; fn < 4; fn++) {
            int row0 = m0 + wm + fm * 16 + g;
            int row1 = row0 + 8;
            int col = n0 + wn + fn * 8 + tg * 2;
            float b0 = bias[col], b1 = bias[col + 1];
            float* a = acc[fm][fn];
            if (MODE == 0) {
                float v0 = fmaxf(a[0] + b0, 0.f), v1 = fmaxf(a[1] + b1, 0.f);
                float v2 = fmaxf(a[2] + b0, 0.f), v3 = fmaxf(a[3] + b1, 0.f);
                *(__half2*)(g_act + (size_t)row0 * N + col) = __floats2half2_rn(v0, v1);
                *(__half2*)(g_act + (size_t)row1 * N + col) = __floats2half2_rn(v2, v3);
            } else {
                size_t i0 = (size_t)row0 * N + col;
                size_t i1 = (size_t)row1 * N + col;
                g_x[i0]     = a[0] + b0 + g_hf32[i0];
                g_x[i0 + 1] = a[1] + b1 + g_hf32[i0 + 1];
                g_x[i1]     = a[2] + b0 + g_hf32[i1];
                g_x[i1 + 1] = a[3] + b1 + g_hf32[i1 + 1];
            }
        }
    }
}

__global__ void k_stats() {
    int i = blockIdx.x;   // token
    int tid = threadIdx.x; // 256
    float4 v = ((const float4*)(g_x + (size_t)i * DD))[tid];
    float4 gv = ((const float4*)g_gl)[tid];
    float s1 = v.x + v.y + v.z + v.w;
    float s2 = v.x * v.x + v.y * v.y + v.z * v.z + v.w * v.w;
    float s3 = v.x * gv.x + v.y * gv.y + v.z * gv.z + v.w * gv.w;
    #pragma unroll
    for (int o = 16; o; o >>= 1) {
        s1 += __shfl_down_sync(0xffffffffu, s1, o);
        s2 += __shfl_down_sync(0xffffffffu, s2, o);
        s3 += __shfl_down_sync(0xffffffffu, s3, o);
    }
    __shared__ float r[3][8];
    int w = tid >> 5, l = tid & 31;
    if (l == 0) { r[0][w] = s1; r[1][w] = s2; r[2][w] = s3; }
    __syncthreads();
    if (tid == 0) {
        float a = 0, b = 0, c = 0;
        #pragma unroll
        for (int j = 0; j < 8; j++) { a += r[0][j]; b += r[1][j]; c += r[2][j]; }
        float* st = g_stats + (size_t)i * 3;
        st[0] = a; st[1] = b; st[2] = c;
    }
}

// per-batch: slot_imp, top-4, rev-2, build mem, layernorm query
__global__ void k_select(const float* __restrict__ ln_g, const float* __restrict__ ln_b,
                         const float* __restrict__ memin) {
    int b = blockIdx.x, tid = threadIdx.x; // 256 threads
    __shared__ float si[TT - 1];
    __shared__ float rv[256];
    __shared__ int   ri[256];
    __shared__ int   s_top[6];
    float sum_gl = g_scal[0], addc = g_scal[1];

    for (int t = tid; t < TT - 1; t += 256) {
        const float* st = g_stats + (size_t)(b * TT + t) * 3;
        float mu = st[0] * (1.f / DD);
        float var = st[1] * (1.f / DD) - mu * mu;
        float rstd = rsqrtf(var + LN_EPS);
        si[t] = rstd * (st[2] - mu * sum_gl) + addc;
    }
    __syncthreads();

    for (int pass = 0; pass < 6; pass++) {
        int lim = (pass < 4) ? (TT - 1) : 8;
        float bv = neg_inf(); int bi = 0x7fffffff;
        for (int t = tid; t < lim; t += 256) {
            float v = si[t];
            if (v > bv || (v == bv && t < bi)) { bv = v; bi = t; }
        }
        rv[tid] = bv; ri[tid] = bi;
        __syncthreads();
        for (int s = 128; s > 0; s >>= 1) {
            if (tid < s) {
                float v = rv[tid + s]; int i2 = ri[tid + s];
                if (v > rv[tid] || (v == rv[tid] && i2 < ri[tid])) { rv[tid] = v; ri[tid] = i2; }
            }
            __syncthreads();
        }
        if (tid == 0) { s_top[pass] = ri[0]; si[ri[0]] = neg_inf(); }
        __syncthreads();
    }

    for (int s = 0; s < SS; s++) {
        int tok = (s < 6) ? s_top[s] : -1;
        if (tok >= 0) {
            const float* st = g_stats + (size_t)(b * TT + tok) * 3;
            float mu = st[0] * (1.f / DD);
            float var = st[1] * (1.f / DD) - mu * mu;
            float rstd = rsqrtf(var + LN_EPS);
            const float* xr = g_x + (size_t)(b * TT + tok) * DD;
            for (int d = tid; d < DD; d += 256)
                g_mem[(size_t)(b * SS + s) * DD + d] = (xr[d] - mu) * rstd * ln_g[d] + ln_b[d];
        } else {
            for (int d = tid; d < DD; d += 256)
                g_mem[(size_t)(b * SS + s) * DD + d] = memin[(size_t)s * DD + d];
        }
    }
    { // query = LN(x[b, T-1])
        int tok = TT - 1;
        const float* st = g_stats + (size_t)(b * TT + tok) * 3;
        float mu = st[0] * (1.f / DD);
        float var = st[1] * (1.f / DD) - mu * mu;
        float rstd = rsqrtf(var + LN_EPS);
        const float* xr = g_x + (size_t)(b * TT + tok) * DD;
        for (int d = tid; d < DD; d += 256) {
            float h = (xr[d] - mu) * rstd * ln_g[d] + ln_b[d];
            g_query[(size_t)b * DD + d] = h;
            g_za[(size_t)b * DD + d] = __float2half(h);
        }
    }
}

__global__ void k_rp(const float* __restrict__ rp_w, const float* __restrict__ rp_b) {
    int b = blockIdx.x, j = threadIdx.x; // 1024 threads
    __shared__ float qs[DD];
    qs[j] = g_query[(size_t)b * DD + j];
    __syncthreads();
    float acc = rp_b[j];
    for (int d = 0; d < DD; d++) acc += qs[d] * rp_w[(size_t)d * DD + j];
    g_q[(size_t)b * DD + j] = acc;
}

__global__ void k_attn() {
    int b = blockIdx.x, tid = threadIdx.x; // 512 threads
    int w = tid >> 5, l = tid & 31;
    __shared__ float sc[SS], at[SS], ssum;
    float acc = 0.f;
    for (int d = l; d < DD; d += 32)
        acc += g_mem[(size_t)(b * SS + w) * DD + d] * g_q[(size_t)b * DD + d];
    #pragma unroll
    for (int o = 16; o; o >>= 1) acc += __shfl_down_sync(0xffffffffu, acc, o);
    if (l == 0) sc[w] = acc;
    __syncthreads();
    if (tid == 0) {
        float mx = sc[0];
        for (int s = 1; s < SS; s++) mx = fmaxf(mx, sc[s]);
        float sm = 0.f;
        for (int s = 0; s < SS; s++) { at[s] = expf(sc[s] - mx); sm += at[s]; }
        ssum = sm;
    }
    __syncthreads();
    float inv = 1.f / ssum;
    for (int d = tid; d < DD; d += 512) {
        float c = 0.f;
        #pragma unroll
        for (int s = 0; s < SS; s++) c += at[s] * g_mem[(size_t)(b * SS + s) * DD + d];
        c *= inv;
        g_za[(size_t)(32 + b) * DD + d] = __float2half(c);
    }
}

// out GEMM: M=64 (query rows 0..31, ctx rows 32..63), N=V, K=1024; B=out_w fp32 converted inline
__global__ void __launch_bounds__(256) k_out(const float* __restrict__ out_w,
                                             const float* __restrict__ out_b) {
    constexpr int BN = 128, BK = 32;
    __shared__ __align__(16) __half As[64 * 40];
    __shared__ __align__(16) __half Bs[BN * 34];
    int tid = threadIdx.x;
    int n0 = blockIdx.x * BN;
    int warp = tid >> 5, lane = tid & 31, g = lane >> 2, tg = lane & 3;
    int wn = warp * 16;
    float acc[4][2][4];
    #pragma unroll
    for (int a = 0; a < 4; a++)
        #pragma unroll
        for (int b2 = 0; b2 < 2; b2++)
            #pragma unroll
            for (int c = 0; c < 4; c++) acc[a][b2][c] = 0.f;

    for (int k0 = 0; k0 < DD; k0 += BK) {
        {
            int row = tid >> 2, c4 = tid & 3;
            uint4 v = *(const uint4*)(g_za + (size_t)row * DD + k0 + c4 * 8);
            *(uint4*)(As + row * 40 + c4 * 8) = v;
        }
        #pragma unroll
        for (int r = 0; r < 16; r++) {
            int lin = r * 256 + tid;
            int k = lin >> 7, n = lin & 127;
            int gc = n0 + n;
            float v = (gc < VV) ? out_w[(size_t)(k0 + k) * VV + gc] : 0.f;
            Bs[n * 34 + k] = __float2half(v);
        }
        __syncthreads();
        #pragma unroll
        for (int kk = 0; kk < BK; kk += 16) {
            uint32_t af[4][4], bf[2][2];
            #pragma unroll
            for (int fm = 0; fm < 4; fm++) {
                const __half* ap = As + (fm * 16) * 40 + kk;
                af[fm][0] = *(const uint32_t*)(ap + g * 40 + tg * 2);
                af[fm][1] = *(const uint32_t*)(ap + (g + 8) * 40 + tg * 2);
                af[fm][2] = *(const uint32_t*)(ap + g * 40 + tg * 2 + 8);
                af[fm][3] = *(const uint32_t*)(ap + (g + 8) * 40 + tg * 2 + 8);
            }
            #pragma unroll
            for (int fn = 0; fn < 2; fn++) {
                const __half* bp = Bs + (wn + fn * 8 + g) * 34 + kk;
                bf[fn][0] = *(const uint32_t*)(bp + tg * 2);
                bf[fn][1] = *(const uint32_t*)(bp + tg * 2 + 8);
            }
            #pragma unroll
            for (int fm = 0; fm < 4; fm++)
                #pragma unroll
                for (int fn = 0; fn < 2; fn++)
                    mma16816(acc[fm][fn], af[fm], bf[fn]);
        }
        __syncthreads();
    }

    #pragma unroll
    for (int fm = 0; fm < 4; fm++) {
        #pragma unroll
        for (int fn = 0; fn < 2; fn++) {
            int r0 = fm * 16 + g, r1 = r0 + 8;
            int col = n0 + wn + fn * 8 + tg * 2;
            float* a = acc[fm][fn];
            #pragma unroll
            for (int co = 0; co < 2; co++) {
                int c = col + co;
                if (c < VV) {
                    float v0 = a[co], v1 = a[2 + co];
                    if (r0 < 32) {
                        g_ld[(size_t)r0 * VV + c] = v0;
                        atomicMaxFloatEnc(&g_bmax[r0], v0 + out_b[c]);
                    } else {
                        g_lc[(size_t)(r0 - 32) * VV + c] = v0;
                    }
                    if (r1 < 32) {
                        g_ld[(size_t)r1 * VV + c] = v1;
                        atomicMaxFloatEnc(&g_bmax[r1], v1 + out_b[c]);
                    } else {
                        g_lc[(size_t)(r1 - 32) * VV + c] = v1;
                    }
                }
            }
        }
    }
}

__global__ void k_sumexp(const float* __restrict__ out_b) {
    int b = blockIdx.y;
    int tid = threadIdx.x; // 256
    float mx = decMax(g_bmax[b]);
    int start = blockIdx.x * 4096;
    int end = start + 4096; if (end > VV) end = VV;
    float s = 0.f;
    for (int v = start + tid; v < end; v += 256)
        s += expf(g_ld[(size_t)b * VV + v] + out_b[v] - mx);
    #pragma unroll
    for (int o = 16; o; o >>= 1) s += __shfl_down_sync(0xffffffffu, s, o);
    __shared__ float r[8];
    int w = tid >> 5, l = tid & 31;
    if (l == 0) r[w] = s;
    __syncthreads();
    if (tid == 0) {
        float t = 0.f;
        #pragma unroll
        for (int j = 0; j < 8; j++) t += r[j];
        atomicAdd(&g_bsum[b], t);
    }
}

__global__ void k_blend(const float* __restrict__ out_b, float* __restrict__ out) {
    size_t i = (size_t)blockIdx.x * 256 + threadIdx.x;
    const size_t total = (size_t)BB * VV;
    if (i >= total) return;
    int b = (int)(i / VV);
    int v = (int)(i % VV);
    float conf = 1.f / g_bsum[b];
    float u = (conf < CONF_TH) ? 1.f : 0.f;
    out[i] = u * g_lc[i] + (1.f - u) * g_ld[i] + out_b[v];
}

// ---------------- launch ----------------
extern "C" void kernel_launch(void* const* d_in, const int* in_sizes, int n_in,
                              void* d_out, int out_size) {
    const int*   seq    = (const int*)  d_in[0];
    const float* embed  = (const float*)d_in[1];
    const float* ff_w1  = (const float*)d_in[2];
    const float* ff_b1  = (const float*)d_in[3];
    const float* ff_w2  = (const float*)d_in[4];
    const float* ff_b2  = (const float*)d_in[5];
    const float* ln_g   = (const float*)d_in[6];
    const float* ln_b   = (const float*)d_in[7];
    const float* wg_w   = (const float*)d_in[8];
    const float* wg_b   = (const float*)d_in[9];
    const float* rp_w   = (const float*)d_in[10];
    const float* rp_b   = (const float*)d_in[11];
    const float* out_w  = (const float*)d_in[12];
    const float* out_b  = (const float*)d_in[13];
    const float* memin  = (const float*)d_in[14];
    float* out = (float*)d_out;

    k_init<<<1, 32>>>();
    k_prep<<<1, 1024>>>(wg_w, wg_b, ln_g, ln_b);
    k_convw<<<4096, 1024>>>(ff_w1, ff_w2);
    k_gather<<<BT, 256>>>(seq, embed);
    k_gemm<0><<<dim3(BT / 128, D2 / 128), 256>>>(ff_b1);
    k_gemm<1><<<dim3(BT / 128, DD / 128), 256>>>(ff_b2);
    k_stats<<<BT, 256>>>();
    k_select<<<BB, 256>>>(ln_g, ln_b, memin);
    k_rp<<<BB, 1024>>>(rp_w, rp_b);
    k_attn<<<BB, 512>>>();
    k_out<<<(VV + 127) / 128, 256>>>(out_w, out_b);
    k_sumexp<<<dim3((VV + 4095) / 4096, BB), 256>>>(out_b);
    {
        size_t total = (size_t)BB * VV;
        k_blend<<<(unsigned)((total + 255) / 256), 256>>>(out_b, out);
    }
}

// round 11
// speedup vs baseline: 1.3047x; 1.3047x over previous
#include <cuda_runtime.h>
#include <cuda_fp16.h>
#include <cstdint>
#include <cstddef>

// ---------------- problem constants ----------------
#define BB 32
#define TT 512
#define DD 1024
#define VV 50257
#define SS 16
#define BT (BB*TT)          // 16384
#define D2 (2*DD)           // 2048
#define LN_EPS 1e-5f
#define CONF_TH 0.8f

// ---------------- scratch (device globals; no allocations allowed) ----------------
__device__ float  g_hf32 [ (size_t)BT * DD ];      // residual h (fp32)
__device__ __half g_hh   [ (size_t)BT * DD ];      // h as fp16 (GEMM A)
__device__ __half g_w1h  [ (size_t)DD * D2 ];      // W1 [1024][2048] fp16 (same layout as input)
__device__ __half g_w2h  [ (size_t)D2 * DD ];      // W2 [2048][1024] fp16
__device__ __half g_act  [ (size_t)BT * D2 ];      // relu(h@W1+b1) fp16
__device__ float  g_x    [ (size_t)BT * DD ];      // h + ff  (pre-LN)
__device__ float  g_stats[ (size_t)BT * 3 ];       // s1, s2, s3 per token
__device__ float  g_gl   [ DD ];                   // ln_g * mean_s(wg_w)
__device__ float  g_scal [ 2 ];                    // {sum_gl, add_const}
__device__ float  g_mem  [ BB * SS * DD ];
__device__ float  g_query[ BB * DD ];
__device__ float  g_q    [ BB * DD ];
__device__ __half g_za   [ 64 * DD ];              // rows 0..31 query, 32..63 ctx (fp16)
__device__ float  g_ld   [ (size_t)BB * VV ];      // direct logits (no bias)
__device__ float  g_lc   [ (size_t)BB * VV ];      // ctx logits (no bias)
__device__ unsigned g_bmax[ BB ];
__device__ float  g_bsum [ BB ];

// ---------------- helpers ----------------
__device__ __forceinline__ uint32_t smem_u32_of(const void* p) {
    uint32_t a;
    asm("{ .reg .u64 t; cvta.to.shared.u64 t, %1; cvt.u32.u64 %0, t; }" : "=r"(a) : "l"(p));
    return a;
}
__device__ __forceinline__ void mma16816(float* c, const uint32_t* a, const uint32_t* b) {
    asm volatile(
        "mma.sync.aligned.m16n8k16.row.col.f32.f16.f16.f32 "
        "{%0,%1,%2,%3},{%4,%5,%6,%7},{%8,%9},{%0,%1,%2,%3};\n"
        : "+f"(c[0]), "+f"(c[1]), "+f"(c[2]), "+f"(c[3])
        : "r"(a[0]), "r"(a[1]), "r"(a[2]), "r"(a[3]), "r"(b[0]), "r"(b[1]));
}
__device__ __forceinline__ void ldsm_x2_trans(uint32_t& r0, uint32_t& r1, uint32_t addr) {
    asm volatile("ldmatrix.sync.aligned.m8n8.x2.trans.shared.b16 {%0, %1}, [%2];"
                 : "=r"(r0), "=r"(r1) : "r"(addr));
}

__device__ __forceinline__ void atomicMaxFloatEnc(unsigned* addr, float val) {
    unsigned u = __float_as_uint(val);
    unsigned enc = (u & 0x80000000u) ? ~u : (u | 0x80000000u);
    atomicMax(addr, enc);
}
__device__ __forceinline__ float decMax(unsigned enc) {
    unsigned u = (enc & 0x80000000u) ? (enc & 0x7FFFFFFFu) : ~enc;
    return __uint_as_float(u);
}
__device__ __forceinline__ float neg_inf() { return __int_as_float(0xff800000); }

// ---------------- kernels ----------------
__global__ void k_init() {
    int t = threadIdx.x;
    if (t < BB) { g_bmax[t] = 0u; g_bsum[t] = 0.f; }
}

// gl[d] = ln_g[d] * mean_s wg_w[d,s];  scal = {sum_d gl, sum_d ln_b*wgm + mean_s wg_b}
__global__ void k_prep(const float* __restrict__ wg_w, const float* __restrict__ wg_b,
                       const float* __restrict__ ln_g, const float* __restrict__ ln_b) {
    int d = threadIdx.x; // 1024
    float wgm = 0.f;
    #pragma unroll
    for (int s = 0; s < SS; s++) wgm += wg_w[d * SS + s];
    wgm *= (1.f / SS);
    float gl = ln_g[d] * wgm;
    g_gl[d] = gl;
    __shared__ float r1[1024], r2[1024];
    r1[d] = gl; r2[d] = ln_b[d] * wgm;
    __syncthreads();
    for (int s = 512; s > 0; s >>= 1) {
        if (d < s) { r1[d] += r1[d + s]; r2[d] += r2[d + s]; }
        __syncthreads();
    }
    if (d == 0) {
        float wb = 0.f;
        for (int s = 0; s < SS; s++) wb += wg_b[s];
        g_scal[0] = r1[0];
        g_scal[1] = r2[0] + wb * (1.f / SS);
    }
}

__global__ void k_convw(const float* __restrict__ w1, const float* __restrict__ w2) {
    size_t i = (size_t)blockIdx.x * blockDim.x + threadIdx.x;  // 4M threads exact
    const size_t NW = (size_t)DD * D2;
    if (i < NW) g_w1h[i] = __float2half(w1[i]);
    else        g_w2h[i - NW] = __float2half(w2[i - NW]);
}

__global__ void k_gather(const int* __restrict__ seq, const float* __restrict__ embed) {
    int i = blockIdx.x;          // token
    int tid = threadIdx.x;       // 256
    int row = seq[i];
    float4 v = ((const float4*)(embed + (size_t)row * DD))[tid];
    ((float4*)(g_hf32 + (size_t)i * DD))[tid] = v;
    __half2* hp = (__half2*)(g_hh + (size_t)i * DD);
    hp[tid * 2]     = __floats2half2_rn(v.x, v.y);
    hp[tid * 2 + 1] = __floats2half2_rn(v.z, v.w);
}

// MODE 0: act = relu(h@W1+b1)  (fp16 out)     N=2048, K=1024
// MODE 1: x = act@W2 + b2 + h  (fp32 out)     N=1024, K=2048
// Identical to the R2-proven kernel EXCEPT the B path: Bs is k-major [BK][136]
// filled with vectorized copies from the (k-major) weight matrix, and B
// fragments come from ldmatrix.x2.trans.
template<int MODE>
__global__ void __launch_bounds__(256) k_gemm(const float* __restrict__ bias) {
    constexpr int N = (MODE == 0) ? D2 : DD;
    constexpr int K = (MODE == 0) ? DD : D2;
    const __half* __restrict__ A  = (MODE == 0) ? g_hh  : g_act;
    const __half* __restrict__ Bm = (MODE == 0) ? g_w1h : g_w2h;

    constexpr int BM = 128, BN = 128, BK = 32;
    constexpr int BSP = 136;   // B smem row stride in halfs (272 B)
    __shared__ __align__(16) __half As[BM * 40];
    __shared__ __align__(16) __half Bs[BK * BSP];

    int tid = threadIdx.x;
    int m0 = blockIdx.x * BM, n0 = blockIdx.y * BN;
    int warp = tid >> 5, lane = tid & 31;
    int wm = (warp >> 2) * 64, wn = (warp & 3) * 32;
    int g = lane >> 2, tg = lane & 3;

    float acc[4][4][4];
    #pragma unroll
    for (int a = 0; a < 4; a++)
        #pragma unroll
        for (int b = 0; b < 4; b++)
            #pragma unroll
            for (int c = 0; c < 4; c++) acc[a][b][c] = 0.f;

    for (int k0 = 0; k0 < K; k0 += BK) {
        // A tile: identical to R2 (proven)
        #pragma unroll
        for (int r = 0; r < 2; r++) {
            int lin = r * 256 + tid;
            int row = lin >> 2, c4 = lin & 3;
            uint4 v = *(const uint4*)(A + (size_t)(m0 + row) * K + k0 + c4 * 8);
            *(uint4*)(As + row * 40 + c4 * 8) = v;
        }
        // B tile: k-major, coalesced. 32 rows x 16 uint4-chunks = 512 chunks.
        #pragma unroll
        for (int r = 0; r < 2; r++) {
            int ci = r * 256 + tid;
            int row = ci >> 4, c = ci & 15;
            uint4 v = *(const uint4*)(Bm + (size_t)(k0 + row) * N + n0 + c * 8);
            *(uint4*)(Bs + row * BSP + c * 8) = v;
        }
        __syncthreads();
        #pragma unroll
        for (int kk = 0; kk < BK; kk += 16) {
            uint32_t af[4][4], bf[4][2];
            #pragma unroll
            for (int fm = 0; fm < 4; fm++) {
                const __half* ap = As + (wm + fm * 16) * 40 + kk;
                af[fm][0] = *(const uint32_t*)(ap + g * 40 + tg * 2);
                af[fm][1] = *(const uint32_t*)(ap + (g + 8) * 40 + tg * 2);
                af[fm][2] = *(const uint32_t*)(ap + g * 40 + tg * 2 + 8);
                af[fm][3] = *(const uint32_t*)(ap + (g + 8) * 40 + tg * 2 + 8);
            }
            // B fragments via ldmatrix.trans from k-major smem.
            // lanes 0-7 address rows kk+0..7 (matrix 0 -> bf[fn][0]),
            // lanes 8-15 rows kk+8..15 (matrix 1 -> bf[fn][1]).
            int ldrow = kk + (lane & 15);
            #pragma unroll
            for (int fn = 0; fn < 4; fn++) {
                uint32_t baddr = smem_u32_of(Bs + ldrow * BSP + wn + fn * 8);
                ldsm_x2_trans(bf[fn][0], bf[fn][1], baddr);
            }
            #pragma unroll
            for (int fm = 0; fm < 4; fm++)
                #pragma unroll
                for (int fn = 0; fn < 4; fn++)
                    mma16816(acc[fm][fn], af[fm], bf[fn]);
        }
        __syncthreads();
    }

    #pragma unroll
    for (int fm = 0; fm < 4; fm++) {
        #pragma unroll
        for (int fn = 0; fn < 4; fn++) {
            int row0 = m0 + wm + fm * 16 + g;
            int row1 = row0 + 8;
            int col = n0 + wn + fn * 8 + tg * 2;
            float b0 = bias[col], b1 = bias[col + 1];
            float* a = acc[fm][fn];
            if (MODE == 0) {
                float v0 = fmaxf(a[0] + b0, 0.f), v1 = fmaxf(a[1] + b1, 0.f);
                float v2 = fmaxf(a[2] + b0, 0.f), v3 = fmaxf(a[3] + b1, 0.f);
                *(__half2*)(g_act + (size_t)row0 * N + col) = __floats2half2_rn(v0, v1);
                *(__half2*)(g_act + (size_t)row1 * N + col) = __floats2half2_rn(v2, v3);
            } else {
                size_t i0 = (size_t)row0 * N + col;
                size_t i1 = (size_t)row1 * N + col;
                g_x[i0]     = a[0] + b0 + g_hf32[i0];
                g_x[i0 + 1] = a[1] + b1 + g_hf32[i0 + 1];
                g_x[i1]     = a[2] + b0 + g_hf32[i1];
                g_x[i1 + 1] = a[3] + b1 + g_hf32[i1 + 1];
            }
        }
    }
}

__global__ void k_stats() {
    int i = blockIdx.x;   // token
    int tid = threadIdx.x; // 256
    float4 v = ((const float4*)(g_x + (size_t)i * DD))[tid];
    float4 gv = ((const float4*)g_gl)[tid];
    float s1 = v.x + v.y + v.z + v.w;
    float s2 = v.x * v.x + v.y * v.y + v.z * v.z + v.w * v.w;
    float s3 = v.x * gv.x + v.y * gv.y + v.z * gv.z + v.w * gv.w;
    #pragma unroll
    for (int o = 16; o; o >>= 1) {
        s1 += __shfl_down_sync(0xffffffffu, s1, o);
        s2 += __shfl_down_sync(0xffffffffu, s2, o);
        s3 += __shfl_down_sync(0xffffffffu, s3, o);
    }
    __shared__ float r[3][8];
    int w = tid >> 5, l = tid & 31;
    if (l == 0) { r[0][w] = s1; r[1][w] = s2; r[2][w] = s3; }
    __syncthreads();
    if (tid == 0) {
        float a = 0, b = 0, c = 0;
        #pragma unroll
        for (int j = 0; j < 8; j++) { a += r[0][j]; b += r[1][j]; c += r[2][j]; }
        float* st = g_stats + (size_t)i * 3;
        st[0] = a; st[1] = b; st[2] = c;
    }
}

// per-batch: slot_imp, top-4, rev-2, build mem, layernorm query
__global__ void k_select(const float* __restrict__ ln_g, const float* __restrict__ ln_b,
                         const float* __restrict__ memin) {
    int b = blockIdx.x, tid = threadIdx.x; // 256 threads
    __shared__ float si[TT - 1];
    __shared__ float rv[256];
    __shared__ int   ri[256];
    __shared__ int   s_top[6];
    float sum_gl = g_scal[0], addc = g_scal[1];

    for (int t = tid; t < TT - 1; t += 256) {
        const float* st = g_stats + (size_t)(b * TT + t) * 3;
        float mu = st[0] * (1.f / DD);
        float var = st[1] * (1.f / DD) - mu * mu;
        float rstd = rsqrtf(var + LN_EPS);
        si[t] = rstd * (st[2] - mu * sum_gl) + addc;
    }
    __syncthreads();

    for (int pass = 0; pass < 6; pass++) {
        int lim = (pass < 4) ? (TT - 1) : 8;
        float bv = neg_inf(); int bi = 0x7fffffff;
        for (int t = tid; t < lim; t += 256) {
            float v = si[t];
            if (v > bv || (v == bv && t < bi)) { bv = v; bi = t; }
        }
        rv[tid] = bv; ri[tid] = bi;
        __syncthreads();
        for (int s = 128; s > 0; s >>= 1) {
            if (tid < s) {
                float v = rv[tid + s]; int i2 = ri[tid + s];
                if (v > rv[tid] || (v == rv[tid] && i2 < ri[tid])) { rv[tid] = v; ri[tid] = i2; }
            }
            __syncthreads();
        }
        if (tid == 0) { s_top[pass] = ri[0]; si[ri[0]] = neg_inf(); }
        __syncthreads();
    }

    for (int s = 0; s < SS; s++) {
        int tok = (s < 6) ? s_top[s] : -1;
        if (tok >= 0) {
            const float* st = g_stats + (size_t)(b * TT + tok) * 3;
            float mu = st[0] * (1.f / DD);
            float var = st[1] * (1.f / DD) - mu * mu;
            float rstd = rsqrtf(var + LN_EPS);
            const float* xr = g_x + (size_t)(b * TT + tok) * DD;
            for (int d = tid; d < DD; d += 256)
                g_mem[(size_t)(b * SS + s) * DD + d] = (xr[d] - mu) * rstd * ln_g[d] + ln_b[d];
        } else {
            for (int d = tid; d < DD; d += 256)
                g_mem[(size_t)(b * SS + s) * DD + d] = memin[(size_t)s * DD + d];
        }
    }
    { // query = LN(x[b, T-1])
        int tok = TT - 1;
        const float* st = g_stats + (size_t)(b * TT + tok) * 3;
        float mu = st[0] * (1.f / DD);
        float var = st[1] * (1.f / DD) - mu * mu;
        float rstd = rsqrtf(var + LN_EPS);
        const float* xr = g_x + (size_t)(b * TT + tok) * DD;
        for (int d = tid; d < DD; d += 256) {
            float h = (xr[d] - mu) * rstd * ln_g[d] + ln_b[d];
            g_query[(size_t)b * DD + d] = h;
            g_za[(size_t)b * DD + d] = __float2half(h);
        }
    }
}

__global__ void k_rp(const float* __restrict__ rp_w, const float* __restrict__ rp_b) {
    int b = blockIdx.x, j = threadIdx.x; // 1024 threads
    __shared__ float qs[DD];
    qs[j] = g_query[(size_t)b * DD + j];
    __syncthreads();
    float acc = rp_b[j];
    for (int d = 0; d < DD; d++) acc += qs[d] * rp_w[(size_t)d * DD + j];
    g_q[(size_t)b * DD + j] = acc;
}

__global__ void k_attn() {
    int b = blockIdx.x, tid = threadIdx.x; // 512 threads
    int w = tid >> 5, l = tid & 31;
    __shared__ float sc[SS], at[SS], ssum;
    float acc = 0.f;
    for (int d = l; d < DD; d += 32)
        acc += g_mem[(size_t)(b * SS + w) * DD + d] * g_q[(size_t)b * DD + d];
    #pragma unroll
    for (int o = 16; o; o >>= 1) acc += __shfl_down_sync(0xffffffffu, acc, o);
    if (l == 0) sc[w] = acc;
    __syncthreads();
    if (tid == 0) {
        float mx = sc[0];
        for (int s = 1; s < SS; s++) mx = fmaxf(mx, sc[s]);
        float sm = 0.f;
        for (int s = 0; s < SS; s++) { at[s] = expf(sc[s] - mx); sm += at[s]; }
        ssum = sm;
    }
    __syncthreads();
    float inv = 1.f / ssum;
    for (int d = tid; d < DD; d += 512) {
        float c = 0.f;
        #pragma unroll
        for (int s = 0; s < SS; s++) c += at[s] * g_mem[(size_t)(b * SS + s) * DD + d];
        c *= inv;
        g_za[(size_t)(32 + b) * DD + d] = __float2half(c);
    }
}

// out GEMM: M=64 (query rows 0..31, ctx rows 32..63), N=V, K=1024; B=out_w fp32 converted inline
__global__ void __launch_bounds__(256) k_out(const float* __restrict__ out_w,
                                             const float* __restrict__ out_b) {
    constexpr int BN = 128, BK = 32;
    __shared__ __align__(16) __half As[64 * 40];
    __shared__ __align__(16) __half Bs[BN * 34];
    int tid = threadIdx.x;
    int n0 = blockIdx.x * BN;
    int warp = tid >> 5, lane = tid & 31, g = lane >> 2, tg = lane & 3;
    int wn = warp * 16;
    float acc[4][2][4];
    #pragma unroll
    for (int a = 0; a < 4; a++)
        #pragma unroll
        for (int b2 = 0; b2 < 2; b2++)
            #pragma unroll
            for (int c = 0; c < 4; c++) acc[a][b2][c] = 0.f;

    for (int k0 = 0; k0 < DD; k0 += BK) {
        {
            int row = tid >> 2, c4 = tid & 3;
            uint4 v = *(const uint4*)(g_za + (size_t)row * DD + k0 + c4 * 8);
            *(uint4*)(As + row * 40 + c4 * 8) = v;
        }
        #pragma unroll
        for (int r = 0; r < 16; r++) {
            int lin = r * 256 + tid;
            int k = lin >> 7, n = lin & 127;
            int gc = n0 + n;
            float v = (gc < VV) ? out_w[(size_t)(k0 + k) * VV + gc] : 0.f;
            Bs[n * 34 + k] = __float2half(v);
        }
        __syncthreads();
        #pragma unroll
        for (int kk = 0; kk < BK; kk += 16) {
            uint32_t af[4][4], bf[2][2];
            #pragma unroll
            for (int fm = 0; fm < 4; fm++) {
                const __half* ap = As + (fm * 16) * 40 + kk;
                af[fm][0] = *(const uint32_t*)(ap + g * 40 + tg * 2);
                af[fm][1] = *(const uint32_t*)(ap + (g + 8) * 40 + tg * 2);
                af[fm][2] = *(const uint32_t*)(ap + g * 40 + tg * 2 + 8);
                af[fm][3] = *(const uint32_t*)(ap + (g + 8) * 40 + tg * 2 + 8);
            }
            #pragma unroll
            for (int fn = 0; fn < 2; fn++) {
                const __half* bp = Bs + (wn + fn * 8 + g) * 34 + kk;
                bf[fn][0] = *(const uint32_t*)(bp + tg * 2);
                bf[fn][1] = *(const uint32_t*)(bp + tg * 2 + 8);
            }
            #pragma unroll
            for (int fm = 0; fm < 4; fm++)
                #pragma unroll
                for (int fn = 0; fn < 2; fn++)
                    mma16816(acc[fm][fn], af[fm], bf[fn]);
        }
        __syncthreads();
    }

    #pragma unroll
    for (int fm = 0; fm < 4; fm++) {
        #pragma unroll
        for (int fn = 0; fn < 2; fn++) {
            int r0 = fm * 16 + g, r1 = r0 + 8;
            int col = n0 + wn + fn * 8 + tg * 2;
            float* a = acc[fm][fn];
            #pragma unroll
            for (int co = 0; co < 2; co++) {
                int c = col + co;
                if (c < VV) {
                    float v0 = a[co], v1 = a[2 + co];
                    if (r0 < 32) {
                        g_ld[(size_t)r0 * VV + c] = v0;
                        atomicMaxFloatEnc(&g_bmax[r0], v0 + out_b[c]);
                    } else {
                        g_lc[(size_t)(r0 - 32) * VV + c] = v0;
                    }
                    if (r1 < 32) {
                        g_ld[(size_t)r1 * VV + c] = v1;
                        atomicMaxFloatEnc(&g_bmax[r1], v1 + out_b[c]);
                    } else {
                        g_lc[(size_t)(r1 - 32) * VV + c] = v1;
                    }
                }
            }
        }
    }
}

__global__ void k_sumexp(const float* __restrict__ out_b) {
    int b = blockIdx.y;
    int tid = threadIdx.x; // 256
    float mx = decMax(g_bmax[b]);
    int start = blockIdx.x * 4096;
    int end = start + 4096; if (end > VV) end = VV;
    float s = 0.f;
    for (int v = start + tid; v < end; v += 256)
        s += expf(g_ld[(size_t)b * VV + v] + out_b[v] - mx);
    #pragma unroll
    for (int o = 16; o; o >>= 1) s += __shfl_down_sync(0xffffffffu, s, o);
    __shared__ float r[8];
    int w = tid >> 5, l = tid & 31;
    if (l == 0) r[w] = s;
    __syncthreads();
    if (tid == 0) {
        float t = 0.f;
        #pragma unroll
        for (int j = 0; j < 8; j++) t += r[j];
        atomicAdd(&g_bsum[b], t);
    }
}

__global__ void k_blend(const float* __restrict__ out_b, float* __restrict__ out) {
    size_t i = (size_t)blockIdx.x * 256 + threadIdx.x;
    const size_t total = (size_t)BB * VV;
    if (i >= total) return;
    int b = (int)(i / VV);
    int v = (int)(i % VV);
    float conf = 1.f / g_bsum[b];
    float u = (conf < CONF_TH) ? 1.f : 0.f;
    out[i] = u * g_lc[i] + (1.f - u) * g_ld[i] + out_b[v];
}

// ---------------- launch ----------------
extern "C" void kernel_launch(void* const* d_in, const int* in_sizes, int n_in,
                              void* d_out, int out_size) {
    const int*   seq    = (const int*)  d_in[0];
    const float* embed  = (const float*)d_in[1];
    const float* ff_w1  = (const float*)d_in[2];
    const float* ff_b1  = (const float*)d_in[3];
    const float* ff_w2  = (const float*)d_in[4];
    const float* ff_b2  = (const float*)d_in[5];
    const float* ln_g   = (const float*)d_in[6];
    const float* ln_b   = (const float*)d_in[7];
    const float* wg_w   = (const float*)d_in[8];
    const float* wg_b   = (const float*)d_in[9];
    const float* rp_w   = (const float*)d_in[10];
    const float* rp_b   = (const float*)d_in[11];
    const float* out_w  = (const float*)d_in[12];
    const float* out_b  = (const float*)d_in[13];
    const float* memin  = (const float*)d_in[14];
    float* out = (float*)d_out;

    k_init<<<1, 32>>>();
    k_prep<<<1, 1024>>>(wg_w, wg_b, ln_g, ln_b);
    k_convw<<<4096, 1024>>>(ff_w1, ff_w2);
    k_gather<<<BT, 256>>>(seq, embed);
    k_gemm<0><<<dim3(BT / 128, D2 / 128), 256>>>(ff_b1);
    k_gemm<1><<<dim3(BT / 128, DD / 128), 256>>>(ff_b2);
    k_stats<<<BT, 256>>>();
    k_select<<<BB, 256>>>(ln_g, ln_b, memin);
    k_rp<<<BB, 1024>>>(rp_w, rp_b);
    k_attn<<<BB, 512>>>();
    k_out<<<(VV + 127) / 128, 256>>>(out_w, out_b);
    k_sumexp<<<dim3((VV + 4095) / 4096, BB), 256>>>(out_b);
    {
        size_t total = (size_t)BB * VV;
        k_blend<<<(unsigned)((total + 255) / 256), 256>>>(out_b, out);
    }
}

// round 12
// speedup vs baseline: 1.4065x; 1.0781x over previous
#include <cuda_runtime.h>
#include <cuda_fp16.h>
#include <cstdint>
#include <cstddef>

// ---------------- problem constants ----------------
#define BB 32
#define TT 512
#define DD 1024
#define VV 50257
#define SS 16
#define BT (BB*TT)          // 16384
#define D2 (2*DD)           // 2048
#define LN_EPS 1e-5f
#define CONF_TH 0.8f

// ---------------- scratch (device globals; no allocations allowed) ----------------
__device__ float  g_hf32 [ (size_t)BT * DD ];      // residual h (fp32)
__device__ __half g_hh   [ (size_t)BT * DD ];      // h as fp16 (GEMM A)
__device__ __half g_w1h  [ (size_t)DD * D2 ];      // W1 [1024][2048] fp16 (same layout as input)
__device__ __half g_w2h  [ (size_t)D2 * DD ];      // W2 [2048][1024] fp16
__device__ __half g_act  [ (size_t)BT * D2 ];      // relu(h@W1+b1) fp16
__device__ float  g_x    [ (size_t)BT * DD ];      // h + ff  (pre-LN)
__device__ float  g_stats[ (size_t)BT * 3 ];       // s1, s2, s3 per token
__device__ float  g_gl   [ DD ];                   // ln_g * mean_s(wg_w)
__device__ float  g_scal [ 2 ];                    // {sum_gl, add_const}
__device__ float  g_mem  [ BB * SS * DD ];
__device__ float  g_query[ BB * DD ];
__device__ float  g_q    [ BB * DD ];
__device__ __half g_za   [ 64 * DD ];              // rows 0..31 query, 32..63 ctx (fp16)
__device__ float  g_ld   [ (size_t)BB * VV ];      // direct logits (no bias)
__device__ float  g_lc   [ (size_t)BB * VV ];      // ctx logits (no bias)
__device__ unsigned g_bmax[ BB ];
__device__ float  g_bsum [ BB ];

// ---------------- helpers ----------------
__device__ __forceinline__ uint32_t smem_u32_of(const void* p) {
    uint32_t a;
    asm("{ .reg .u64 t; cvta.to.shared.u64 t, %1; cvt.u32.u64 %0, t; }" : "=r"(a) : "l"(p));
    return a;
}
__device__ __forceinline__ void mma16816(float* c, const uint32_t* a, const uint32_t* b) {
    asm volatile(
        "mma.sync.aligned.m16n8k16.row.col.f32.f16.f16.f32 "
        "{%0,%1,%2,%3},{%4,%5,%6,%7},{%8,%9},{%0,%1,%2,%3};\n"
        : "+f"(c[0]), "+f"(c[1]), "+f"(c[2]), "+f"(c[3])
        : "r"(a[0]), "r"(a[1]), "r"(a[2]), "r"(a[3]), "r"(b[0]), "r"(b[1]));
}
__device__ __forceinline__ void ldsm_x2_trans(uint32_t& r0, uint32_t& r1, uint32_t addr) {
    asm volatile("ldmatrix.sync.aligned.m8n8.x2.trans.shared.b16 {%0, %1}, [%2];"
                 : "=r"(r0), "=r"(r1) : "r"(addr));
}
__device__ __forceinline__ void cp16(uint32_t smem_addr, const void* gptr) {
    asm volatile("cp.async.cg.shared.global [%0], [%1], 16;\n" :: "r"(smem_addr), "l"(gptr));
}
__device__ __forceinline__ void cp_commit() { asm volatile("cp.async.commit_group;" ::: "memory"); }
__device__ __forceinline__ void cp_wait0()  { asm volatile("cp.async.wait_group 0;" ::: "memory"); }

__device__ __forceinline__ void atomicMaxFloatEnc(unsigned* addr, float val) {
    unsigned u = __float_as_uint(val);
    unsigned enc = (u & 0x80000000u) ? ~u : (u | 0x80000000u);
    atomicMax(addr, enc);
}
__device__ __forceinline__ float decMax(unsigned enc) {
    unsigned u = (enc & 0x80000000u) ? (enc & 0x7FFFFFFFu) : ~enc;
    return __uint_as_float(u);
}
__device__ __forceinline__ float neg_inf() { return __int_as_float(0xff800000); }

// ---------------- kernels ----------------
__global__ void k_init() {
    int t = threadIdx.x;
    if (t < BB) { g_bmax[t] = 0u; g_bsum[t] = 0.f; }
}

// gl[d] = ln_g[d] * mean_s wg_w[d,s];  scal = {sum_d gl, sum_d ln_b*wgm + mean_s wg_b}
__global__ void k_prep(const float* __restrict__ wg_w, const float* __restrict__ wg_b,
                       const float* __restrict__ ln_g, const float* __restrict__ ln_b) {
    int d = threadIdx.x; // 1024
    float wgm = 0.f;
    #pragma unroll
    for (int s = 0; s < SS; s++) wgm += wg_w[d * SS + s];
    wgm *= (1.f / SS);
    float gl = ln_g[d] * wgm;
    g_gl[d] = gl;
    __shared__ float r1[1024], r2[1024];
    r1[d] = gl; r2[d] = ln_b[d] * wgm;
    __syncthreads();
    for (int s = 512; s > 0; s >>= 1) {
        if (d < s) { r1[d] += r1[d + s]; r2[d] += r2[d + s]; }
        __syncthreads();
    }
    if (d == 0) {
        float wb = 0.f;
        for (int s = 0; s < SS; s++) wb += wg_b[s];
        g_scal[0] = r1[0];
        g_scal[1] = r2[0] + wb * (1.f / SS);
    }
}

__global__ void k_convw(const float* __restrict__ w1, const float* __restrict__ w2) {
    size_t i = (size_t)blockIdx.x * blockDim.x + threadIdx.x;  // 4M threads exact
    const size_t NW = (size_t)DD * D2;
    if (i < NW) g_w1h[i] = __float2half(w1[i]);
    else        g_w2h[i - NW] = __float2half(w2[i - NW]);
}

__global__ void k_gather(const int* __restrict__ seq, const float* __restrict__ embed) {
    int i = blockIdx.x;          // token
    int tid = threadIdx.x;       // 256
    int row = seq[i];
    float4 v = ((const float4*)(embed + (size_t)row * DD))[tid];
    ((float4*)(g_hf32 + (size_t)i * DD))[tid] = v;
    __half2* hp = (__half2*)(g_hh + (size_t)i * DD);
    hp[tid * 2]     = __floats2half2_rn(v.x, v.y);
    hp[tid * 2 + 1] = __floats2half2_rn(v.z, v.w);
}

// MODE 0: act = relu(h@W1+b1)  (fp16 out)     N=2048, K=1024
// MODE 1: x = act@W2 + b2 + h  (fp32 out)     N=1024, K=2048
// R11-proven kernel with ONE change: loads are cp.async into double buffers,
// next tile issued before computing the current one. Fragment/MMA/epilogue
// code and all data values identical to R11.
template<int MODE>
__global__ void __launch_bounds__(256) k_gemm(const float* __restrict__ bias) {
    constexpr int N = (MODE == 0) ? D2 : DD;
    constexpr int K = (MODE == 0) ? DD : D2;
    constexpr int KT = K / 32;
    const __half* __restrict__ A  = (MODE == 0) ? g_hh  : g_act;
    const __half* __restrict__ Bm = (MODE == 0) ? g_w1h : g_w2h;

    constexpr int BM = 128, BN = 128, BK = 32;
    constexpr int BSP = 136;   // B smem row stride in halfs (272 B)
    __shared__ __align__(16) __half As[2][BM * 40];
    __shared__ __align__(16) __half Bs[2][BK * BSP];

    int tid = threadIdx.x;
    int m0 = blockIdx.x * BM, n0 = blockIdx.y * BN;
    int warp = tid >> 5, lane = tid & 31;
    int wm = (warp >> 2) * 64, wn = (warp & 3) * 32;
    int g = lane >> 2, tg = lane & 3;

    float acc[4][4][4];
    #pragma unroll
    for (int a = 0; a < 4; a++)
        #pragma unroll
        for (int b = 0; b < 4; b++)
            #pragma unroll
            for (int c = 0; c < 4; c++) acc[a][b][c] = 0.f;

    auto load_tile = [&](int buf, int k0) {
        // A tile: same addressing as R11, via cp.async
        #pragma unroll
        for (int r = 0; r < 2; r++) {
            int lin = r * 256 + tid;
            int row = lin >> 2, c4 = lin & 3;
            cp16(smem_u32_of(As[buf] + row * 40 + c4 * 8),
                 A + (size_t)(m0 + row) * K + k0 + c4 * 8);
        }
        // B tile: same addressing as R11, via cp.async
        #pragma unroll
        for (int r = 0; r < 2; r++) {
            int ci = r * 256 + tid;
            int row = ci >> 4, c = ci & 15;
            cp16(smem_u32_of(Bs[buf] + row * BSP + c * 8),
                 Bm + (size_t)(k0 + row) * N + n0 + c * 8);
        }
    };

    load_tile(0, 0);
    cp_commit();

    for (int kt = 0; kt < KT; kt++) {
        cp_wait0();          // tile kt resident (it's the only group in flight)
        __syncthreads();     // visibility across threads + back-edge barrier for buffer reuse

        if (kt + 1 < KT) {   // prefetch next tile into the other buffer, overlapping compute
            load_tile((kt + 1) & 1, (kt + 1) * BK);
            cp_commit();
        }

        const __half* as = As[kt & 1];
        const __half* bs = Bs[kt & 1];

        #pragma unroll
        for (int kk = 0; kk < BK; kk += 16) {
            uint32_t af[4][4], bf[4][2];
            #pragma unroll
            for (int fm = 0; fm < 4; fm++) {
                const __half* ap = as + (wm + fm * 16) * 40 + kk;
                af[fm][0] = *(const uint32_t*)(ap + g * 40 + tg * 2);
                af[fm][1] = *(const uint32_t*)(ap + (g + 8) * 40 + tg * 2);
                af[fm][2] = *(const uint32_t*)(ap + g * 40 + tg * 2 + 8);
                af[fm][3] = *(const uint32_t*)(ap + (g + 8) * 40 + tg * 2 + 8);
            }
            int ldrow = kk + (lane & 15);
            #pragma unroll
            for (int fn = 0; fn < 4; fn++) {
                uint32_t baddr = smem_u32_of(bs + ldrow * BSP + wn + fn * 8);
                ldsm_x2_trans(bf[fn][0], bf[fn][1], baddr);
            }
            #pragma unroll
            for (int fm = 0; fm < 4; fm++)
                #pragma unroll
                for (int fn = 0; fn < 4; fn++)
                    mma16816(acc[fm][fn], af[fm], bf[fn]);
        }
    }

    #pragma unroll
    for (int fm = 0; fm < 4; fm++) {
        #pragma unroll
        for (int fn = 0; fn < 4; fn++) {
            int row0 = m0 + wm + fm * 16 + g;
            int row1 = row0 + 8;
            int col = n0 + wn + fn * 8 + tg * 2;
            float b0 = bias[col], b1 = bias[col + 1];
            float* a = acc[fm][fn];
            if (MODE == 0) {
                float v0 = fmaxf(a[0] + b0, 0.f), v1 = fmaxf(a[1] + b1, 0.f);
                float v2 = fmaxf(a[2] + b0, 0.f), v3 = fmaxf(a[3] + b1, 0.f);
                *(__half2*)(g_act + (size_t)row0 * N + col) = __floats2half2_rn(v0, v1);
                *(__half2*)(g_act + (size_t)row1 * N + col) = __floats2half2_rn(v2, v3);
            } else {
                size_t i0 = (size_t)row0 * N + col;
                size_t i1 = (size_t)row1 * N + col;
                g_x[i0]     = a[0] + b0 + g_hf32[i0];
                g_x[i0 + 1] = a[1] + b1 + g_hf32[i0 + 1];
                g_x[i1]     = a[2] + b0 + g_hf32[i1];
                g_x[i1 + 1] = a[3] + b1 + g_hf32[i1 + 1];
            }
        }
    }
}

__global__ void k_stats() {
    int i = blockIdx.x;   // token
    int tid = threadIdx.x; // 256
    float4 v = ((const float4*)(g_x + (size_t)i * DD))[tid];
    float4 gv = ((const float4*)g_gl)[tid];
    float s1 = v.x + v.y + v.z + v.w;
    float s2 = v.x * v.x + v.y * v.y + v.z * v.z + v.w * v.w;
    float s3 = v.x * gv.x + v.y * gv.y + v.z * gv.z + v.w * gv.w;
    #pragma unroll
    for (int o = 16; o; o >>= 1) {
        s1 += __shfl_down_sync(0xffffffffu, s1, o);
        s2 += __shfl_down_sync(0xffffffffu, s2, o);
        s3 += __shfl_down_sync(0xffffffffu, s3, o);
    }
    __shared__ float r[3][8];
    int w = tid >> 5, l = tid & 31;
    if (l == 0) { r[0][w] = s1; r[1][w] = s2; r[2][w] = s3; }
    __syncthreads();
    if (tid == 0) {
        float a = 0, b = 0, c = 0;
        #pragma unroll
        for (int j = 0; j < 8; j++) { a += r[0][j]; b += r[1][j]; c += r[2][j]; }
        float* st = g_stats + (size_t)i * 3;
        st[0] = a; st[1] = b; st[2] = c;
    }
}

// per-batch: slot_imp, top-4, rev-2, build mem, layernorm query
__global__ void k_select(const float* __restrict__ ln_g, const float* __restrict__ ln_b,
                         const float* __restrict__ memin) {
    int b = blockIdx.x, tid = threadIdx.x; // 256 threads
    __shared__ float si[TT - 1];
    __shared__ float rv[256];
    __shared__ int   ri[256];
    __shared__ int   s_top[6];
    float sum_gl = g_scal[0], addc = g_scal[1];

    for (int t = tid; t < TT - 1; t += 256) {
        const float* st = g_stats + (size_t)(b * TT + t) * 3;
        float mu = st[0] * (1.f / DD);
        float var = st[1] * (1.f / DD) - mu * mu;
        float rstd = rsqrtf(var + LN_EPS);
        si[t] = rstd * (st[2] - mu * sum_gl) + addc;
    }
    __syncthreads();

    for (int pass = 0; pass < 6; pass++) {
        int lim = (pass < 4) ? (TT - 1) : 8;
        float bv = neg_inf(); int bi = 0x7fffffff;
        for (int t = tid; t < lim; t += 256) {
            float v = si[t];
            if (v > bv || (v == bv && t < bi)) { bv = v; bi = t; }
        }
        rv[tid] = bv; ri[tid] = bi;
        __syncthreads();
        for (int s = 128; s > 0; s >>= 1) {
            if (tid < s) {
                float v = rv[tid + s]; int i2 = ri[tid + s];
                if (v > rv[tid] || (v == rv[tid] && i2 < ri[tid])) { rv[tid] = v; ri[tid] = i2; }
            }
            __syncthreads();
        }
        if (tid == 0) { s_top[pass] = ri[0]; si[ri[0]] = neg_inf(); }
        __syncthreads();
    }

    for (int s = 0; s < SS; s++) {
        int tok = (s < 6) ? s_top[s] : -1;
        if (tok >= 0) {
            const float* st = g_stats + (size_t)(b * TT + tok) * 3;
            float mu = st[0] * (1.f / DD);
            float var = st[1] * (1.f / DD) - mu * mu;
            float rstd = rsqrtf(var + LN_EPS);
            const float* xr = g_x + (size_t)(b * TT + tok) * DD;
            for (int d = tid; d < DD; d += 256)
                g_mem[(size_t)(b * SS + s) * DD + d] = (xr[d] - mu) * rstd * ln_g[d] + ln_b[d];
        } else {
            for (int d = tid; d < DD; d += 256)
                g_mem[(size_t)(b * SS + s) * DD + d] = memin[(size_t)s * DD + d];
        }
    }
    { // query = LN(x[b, T-1])
        int tok = TT - 1;
        const float* st = g_stats + (size_t)(b * TT + tok) * 3;
        float mu = st[0] * (1.f / DD);
        float var = st[1] * (1.f / DD) - mu * mu;
        float rstd = rsqrtf(var + LN_EPS);
        const float* xr = g_x + (size_t)(b * TT + tok) * DD;
        for (int d = tid; d < DD; d += 256) {
            float h = (xr[d] - mu) * rstd * ln_g[d] + ln_b[d];
            g_query[(size_t)b * DD + d] = h;
            g_za[(size_t)b * DD + d] = __float2half(h);
        }
    }
}

__global__ void k_rp(const float* __restrict__ rp_w, const float* __restrict__ rp_b) {
    int b = blockIdx.x, j = threadIdx.x; // 1024 threads
    __shared__ float qs[DD];
    qs[j] = g_query[(size_t)b * DD + j];
    __syncthreads();
    float acc = rp_b[j];
    for (int d = 0; d < DD; d++) acc += qs[d] * rp_w[(size_t)d * DD + j];
    g_q[(size_t)b * DD + j] = acc;
}

__global__ void k_attn() {
    int b = blockIdx.x, tid = threadIdx.x; // 512 threads
    int w = tid >> 5, l = tid & 31;
    __shared__ float sc[SS], at[SS], ssum;
    float acc = 0.f;
    for (int d = l; d < DD; d += 32)
        acc += g_mem[(size_t)(b * SS + w) * DD + d] * g_q[(size_t)b * DD + d];
    #pragma unroll
    for (int o = 16; o; o >>= 1) acc += __shfl_down_sync(0xffffffffu, acc, o);
    if (l == 0) sc[w] = acc;
    __syncthreads();
    if (tid == 0) {
        float mx = sc[0];
        for (int s = 1; s < SS; s++) mx = fmaxf(mx, sc[s]);
        float sm = 0.f;
        for (int s = 0; s < SS; s++) { at[s] = expf(sc[s] - mx); sm += at[s]; }
        ssum = sm;
    }
    __syncthreads();
    float inv = 1.f / ssum;
    for (int d = tid; d < DD; d += 512) {
        float c = 0.f;
        #pragma unroll
        for (int s = 0; s < SS; s++) c += at[s] * g_mem[(size_t)(b * SS + s) * DD + d];
        c *= inv;
        g_za[(size_t)(32 + b) * DD + d] = __float2half(c);
    }
}

// out GEMM: M=64 (query rows 0..31, ctx rows 32..63), N=V, K=1024; B=out_w fp32 converted inline
__global__ void __launch_bounds__(256) k_out(const float* __restrict__ out_w,
                                             const float* __restrict__ out_b) {
    constexpr int BN = 128, BK = 32;
    __shared__ __align__(16) __half As[64 * 40];
    __shared__ __align__(16) __half Bs[BN * 34];
    int tid = threadIdx.x;
    int n0 = blockIdx.x * BN;
    int warp = tid >> 5, lane = tid & 31, g = lane >> 2, tg = lane & 3;
    int wn = warp * 16;
    float acc[4][2][4];
    #pragma unroll
    for (int a = 0; a < 4; a++)
        #pragma unroll
        for (int b2 = 0; b2 < 2; b2++)
            #pragma unroll
            for (int c = 0; c < 4; c++) acc[a][b2][c] = 0.f;

    for (int k0 = 0; k0 < DD; k0 += BK) {
        {
            int row = tid >> 2, c4 = tid & 3;
            uint4 v = *(const uint4*)(g_za + (size_t)row * DD + k0 + c4 * 8);
            *(uint4*)(As + row * 40 + c4 * 8) = v;
        }
        #pragma unroll
        for (int r = 0; r < 16; r++) {
            int lin = r * 256 + tid;
            int k = lin >> 7, n = lin & 127;
            int gc = n0 + n;
            float v = (gc < VV) ? out_w[(size_t)(k0 + k) * VV + gc] : 0.f;
            Bs[n * 34 + k] = __float2half(v);
        }
        __syncthreads();
        #pragma unroll
        for (int kk = 0; kk < BK; kk += 16) {
            uint32_t af[4][4], bf[2][2];
            #pragma unroll
            for (int fm = 0; fm < 4; fm++) {
                const __half* ap = As + (fm * 16) * 40 + kk;
                af[fm][0] = *(const uint32_t*)(ap + g * 40 + tg * 2);
                af[fm][1] = *(const uint32_t*)(ap + (g + 8) * 40 + tg * 2);
                af[fm][2] = *(const uint32_t*)(ap + g * 40 + tg * 2 + 8);
                af[fm][3] = *(const uint32_t*)(ap + (g + 8) * 40 + tg * 2 + 8);
            }
            #pragma unroll
            for (int fn = 0; fn < 2; fn++) {
                const __half* bp = Bs + (wn + fn * 8 + g) * 34 + kk;
                bf[fn][0] = *(const uint32_t*)(bp + tg * 2);
                bf[fn][1] = *(const uint32_t*)(bp + tg * 2 + 8);
            }
            #pragma unroll
            for (int fm = 0; fm < 4; fm++)
                #pragma unroll
                for (int fn = 0; fn < 2; fn++)
                    mma16816(acc[fm][fn], af[fm], bf[fn]);
        }
        __syncthreads();
    }

    #pragma unroll
    for (int fm = 0; fm < 4; fm++) {
        #pragma unroll
        for (int fn = 0; fn < 2; fn++) {
            int r0 = fm * 16 + g, r1 = r0 + 8;
            int col = n0 + wn + fn * 8 + tg * 2;
            float* a = acc[fm][fn];
            #pragma unroll
            for (int co = 0; co < 2; co++) {
                int c = col + co;
                if (c < VV) {
                    float v0 = a[co], v1 = a[2 + co];
                    if (r0 < 32) {
                        g_ld[(size_t)r0 * VV + c] = v0;
                        atomicMaxFloatEnc(&g_bmax[r0], v0 + out_b[c]);
                    } else {
                        g_lc[(size_t)(r0 - 32) * VV + c] = v0;
                    }
                    if (r1 < 32) {
                        g_ld[(size_t)r1 * VV + c] = v1;
                        atomicMaxFloatEnc(&g_bmax[r1], v1 + out_b[c]);
                    } else {
                        g_lc[(size_t)(r1 - 32) * VV + c] = v1;
                    }
                }
            }
        }
    }
}

__global__ void k_sumexp(const float* __restrict__ out_b) {
    int b = blockIdx.y;
    int tid = threadIdx.x; // 256
    float mx = decMax(g_bmax[b]);
    int start = blockIdx.x * 4096;
    int end = start + 4096; if (end > VV) end = VV;
    float s = 0.f;
    for (int v = start + tid; v < end; v += 256)
        s += expf(g_ld[(size_t)b * VV + v] + out_b[v] - mx);
    #pragma unroll
    for (int o = 16; o; o >>= 1) s += __shfl_down_sync(0xffffffffu, s, o);
    __shared__ float r[8];
    int w = tid >> 5, l = tid & 31;
    if (l == 0) r[w] = s;
    __syncthreads();
    if (tid == 0) {
        float t = 0.f;
        #pragma unroll
        for (int j = 0; j < 8; j++) t += r[j];
        atomicAdd(&g_bsum[b], t);
    }
}

__global__ void k_blend(const float* __restrict__ out_b, float* __restrict__ out) {
    size_t i = (size_t)blockIdx.x * 256 + threadIdx.x;
    const size_t total = (size_t)BB * VV;
    if (i >= total) return;
    int b = (int)(i / VV);
    int v = (int)(i % VV);
    float conf = 1.f / g_bsum[b];
    float u = (conf < CONF_TH) ? 1.f : 0.f;
    out[i] = u * g_lc[i] + (1.f - u) * g_ld[i] + out_b[v];
}

// ---------------- launch ----------------
extern "C" void kernel_launch(void* const* d_in, const int* in_sizes, int n_in,
                              void* d_out, int out_size) {
    const int*   seq    = (const int*)  d_in[0];
    const float* embed  = (const float*)d_in[1];
    const float* ff_w1  = (const float*)d_in[2];
    const float* ff_b1  = (const float*)d_in[3];
    const float* ff_w2  = (const float*)d_in[4];
    const float* ff_b2  = (const float*)d_in[5];
    const float* ln_g   = (const float*)d_in[6];
    const float* ln_b   = (const float*)d_in[7];
    const float* wg_w   = (const float*)d_in[8];
    const float* wg_b   = (const float*)d_in[9];
    const float* rp_w   = (const float*)d_in[10];
    const float* rp_b   = (const float*)d_in[11];
    const float* out_w  = (const float*)d_in[12];
    const float* out_b  = (const float*)d_in[13];
    const float* memin  = (const float*)d_in[14];
    float* out = (float*)d_out;

    k_init<<<1, 32>>>();
    k_prep<<<1, 1024>>>(wg_w, wg_b, ln_g, ln_b);
    k_convw<<<4096, 1024>>>(ff_w1, ff_w2);
    k_gather<<<BT, 256>>>(seq, embed);
    k_gemm<0><<<dim3(BT / 128, D2 / 128), 256>>>(ff_b1);
    k_gemm<1><<<dim3(BT / 128, DD / 128), 256>>>(ff_b2);
    k_stats<<<BT, 256>>>();
    k_select<<<BB, 256>>>(ln_g, ln_b, memin);
    k_rp<<<BB, 1024>>>(rp_w, rp_b);
    k_attn<<<BB, 512>>>();
    k_out<<<(VV + 127) / 128, 256>>>(out_w, out_b);
    k_sumexp<<<dim3((VV + 4095) / 4096, BB), 256>>>(out_b);
    {
        size_t total = (size_t)BB * VV;
        k_blend<<<(unsigned)((total + 255) / 256), 256>>>(out_b, out);
    }
}